// round 3
// baseline (speedup 1.0000x reference)
#include <cuda_runtime.h>
#include <cstdint>

#define MAXC 10016
#define EMB 32

// Scratch (allocation-free rule: __device__ globals)
__device__ __align__(16) float4 d_sumR[MAXC * 8];   // per-candidate sum of relu(a*p+q), 32 floats
__device__ float d_cnt[MAXC];
__device__ __align__(16) float d_G[MAXC * EMB];     // per-candidate gather table (q1 folded in)
__device__ float d_p[EMB], d_q[EMB], d_p1[EMB];
__device__ float d_u[EMB];
__device__ __align__(16) float d_W[EMB * EMB];      // w_t2 @ w_u1_bot
__device__ float d_q1v[EMB];

// ---------------------------------------------------------------------------
// Precompute folded weights (tiny, 1 block)
// ---------------------------------------------------------------------------
__global__ void precompute_kernel(const float* __restrict__ w_v2h,
                                  const float* __restrict__ b_v2h,
                                  const float* __restrict__ w_t1,
                                  const float* __restrict__ b_t1,
                                  const float* __restrict__ w_t2,
                                  const float* __restrict__ b_t2,
                                  const float* __restrict__ w_u1,
                                  const float* __restrict__ b_u1)
{
    int tid = threadIdx.x;           // 1024 threads
    int m = tid >> 5, k = tid & 31;

    // W[m][k] = sum_j w_t2[m][j] * w_u1[32+j][k]
    float w = 0.f;
    #pragma unroll
    for (int j = 0; j < EMB; j++)
        w += w_t2[m * EMB + j] * w_u1[(EMB + j) * EMB + k];
    d_W[m * EMB + k] = w;

    if (m == 0) {
        float u = 0.f;
        #pragma unroll
        for (int j = 0; j < EMB; j++)
            u += b_t2[j] * w_u1[(EMB + j) * EMB + k];
        d_u[k] = u;

        float p = 0.f, q = 0.f, p1 = 0.f, q1 = 0.f;
        #pragma unroll
        for (int i = 0; i < EMB; i++) {
            float v = w_v2h[i];
            float b = b_v2h[i];
            p  += v * w_t1[i * EMB + k];
            q  += b * w_t1[i * EMB + k];
            p1 += v * w_u1[i * EMB + k];
            q1 += b * w_u1[i * EMB + k];
        }
        d_p[k]   = p;
        d_q[k]   = q + b_t1[k];
        d_p1[k]  = p1;
        d_q1v[k] = q1 + b_u1[k];
    }
}

// ---------------------------------------------------------------------------
// Pass 1: per-edge relu(a*p+q), scatter-add into d_sumR[src], count edges
// ---------------------------------------------------------------------------
__global__ __launch_bounds__(256) void pass1_kernel(
    const float* __restrict__ edge_attr,
    const int* __restrict__ src,
    int E)
{
    __shared__ float sp[EMB], sq[EMB];
    if (threadIdx.x < EMB) {
        sp[threadIdx.x] = d_p[threadIdx.x];
        sq[threadIdx.x] = d_q[threadIdx.x];
    }
    __syncthreads();

    int e = blockIdx.x * blockDim.x + threadIdx.x;
    if (e >= E) return;

    float a = edge_attr[e];
    int c = src[e];
    float4* base = d_sumR + c * 8;

    #pragma unroll
    for (int i = 0; i < 8; i++) {
        float r0 = fmaxf(fmaf(a, sp[4 * i + 0], sq[4 * i + 0]), 0.f);
        float r1 = fmaxf(fmaf(a, sp[4 * i + 1], sq[4 * i + 1]), 0.f);
        float r2 = fmaxf(fmaf(a, sp[4 * i + 2], sq[4 * i + 2]), 0.f);
        float r3 = fmaxf(fmaf(a, sp[4 * i + 3], sq[4 * i + 3]), 0.f);
        asm volatile("red.global.add.v4.f32 [%0], {%1, %2, %3, %4};"
                     :: "l"(base + i), "f"(r0), "f"(r1), "f"(r2), "f"(r3)
                     : "memory");
    }
    atomicAdd(&d_cnt[c], 1.0f);
}

// ---------------------------------------------------------------------------
// Per-candidate: G[c][k] = q1[k] + cnt[c]*u[k] + sum_m sumR[c][m]*W[m][k]
// ---------------------------------------------------------------------------
__global__ __launch_bounds__(256) void gtable_kernel(int C)
{
    int idx = blockIdx.x * blockDim.x + threadIdx.x;
    if (idx >= C * EMB) return;
    int c = idx >> 5, k = idx & 31;

    const float* sr = (const float*)(d_sumR + c * 8);
    float acc = d_q1v[k] + d_cnt[c] * d_u[k];
    #pragma unroll
    for (int m = 0; m < EMB; m++)
        acc = fmaf(sr[m], d_W[m * EMB + k], acc);
    d_G[idx] = acc;
}

// ---------------------------------------------------------------------------
// Pass 2: out[e] = relu(a*p1 + G[src]) @ w_u2 + b_u2  (packed f32x2 FMA)
// ---------------------------------------------------------------------------
__global__ __launch_bounds__(256) void pass2_kernel(
    const float* __restrict__ edge_attr,
    const int* __restrict__ src,
    const float* __restrict__ w_u2,
    const float* __restrict__ b_u2,
    float* __restrict__ out,
    int E)
{
    __shared__ unsigned long long sw[EMB * 16];   // w_u2 as packed pairs
    __shared__ unsigned long long sb[16];         // b_u2 as packed pairs
    __shared__ float sp1[EMB];

    for (int i = threadIdx.x; i < EMB * 16; i += blockDim.x)
        sw[i] = ((const unsigned long long*)w_u2)[i];
    if (threadIdx.x < 16)
        sb[threadIdx.x] = ((const unsigned long long*)b_u2)[threadIdx.x];
    if (threadIdx.x < EMB)
        sp1[threadIdx.x] = d_p1[threadIdx.x];
    __syncthreads();

    int e = blockIdx.x * blockDim.x + threadIdx.x;
    if (e >= E) return;

    float a = edge_attr[e];
    int c = src[e];

    // gather G row (L2-resident, 1.28 MB table)
    float4 g[8];
    const float4* gp = (const float4*)d_G + c * 8;
    #pragma unroll
    for (int i = 0; i < 8; i++) g[i] = gp[i];

    unsigned long long acc[16];
    #pragma unroll
    for (int kk = 0; kk < 16; kk++) acc[kk] = sb[kk];

    const float* gf = (const float*)g;
    #pragma unroll
    for (int j = 0; j < EMB; j++) {
        float zj = fmaxf(fmaf(a, sp1[j], gf[j]), 0.f);
        unsigned long long zz;
        asm("mov.b64 %0, {%1, %1};" : "=l"(zz) : "f"(zj));
        #pragma unroll
        for (int kk = 0; kk < 16; kk++) {
            asm("fma.rn.f32x2 %0, %1, %2, %0;"
                : "+l"(acc[kk]) : "l"(zz), "l"(sw[j * 16 + kk]));
        }
    }

    float4* op = (float4*)(out + (size_t)e * EMB);
    #pragma unroll
    for (int i = 0; i < 8; i++) {
        float lo0, hi0, lo1, hi1;
        asm("mov.b64 {%0, %1}, %2;" : "=f"(lo0), "=f"(hi0) : "l"(acc[2 * i]));
        asm("mov.b64 {%0, %1}, %2;" : "=f"(lo1), "=f"(hi1) : "l"(acc[2 * i + 1]));
        op[i] = make_float4(lo0, hi0, lo1, hi1);
    }
}

// ---------------------------------------------------------------------------
extern "C" void kernel_launch(void* const* d_in, const int* in_sizes, int n_in,
                              void* d_out, int out_size)
{
    const float* edge_attr  = (const float*)d_in[0];
    const int*   edge_index = (const int*)d_in[1];   // [2, E] int32 (JAX x64 disabled); row 0 = src
    const float* w_v2h = (const float*)d_in[3];
    const float* b_v2h = (const float*)d_in[4];
    const float* w_t1  = (const float*)d_in[5];
    const float* b_t1  = (const float*)d_in[6];
    const float* w_t2  = (const float*)d_in[7];
    const float* b_t2  = (const float*)d_in[8];
    const float* w_u1  = (const float*)d_in[9];
    const float* b_u1  = (const float*)d_in[10];
    const float* w_u2  = (const float*)d_in[11];
    const float* b_u2  = (const float*)d_in[12];
    float*       out   = (float*)d_out;

    int E = in_sizes[0];   // edge_attr is [E,1]
    int C = in_sizes[2];   // candidate_idxs count

    void *sumR_ptr = nullptr, *cnt_ptr = nullptr;
    cudaGetSymbolAddress(&sumR_ptr, d_sumR);
    cudaGetSymbolAddress(&cnt_ptr, d_cnt);

    cudaMemsetAsync(sumR_ptr, 0, (size_t)C * EMB * sizeof(float), 0);
    cudaMemsetAsync(cnt_ptr, 0, (size_t)C * sizeof(float), 0);

    precompute_kernel<<<1, 1024, 0, 0>>>(w_v2h, b_v2h, w_t1, b_t1,
                                         w_t2, b_t2, w_u1, b_u1);

    int blocks = (E + 255) / 256;
    pass1_kernel<<<blocks, 256, 0, 0>>>(edge_attr, edge_index, E);

    int gblocks = (C * EMB + 255) / 256;
    gtable_kernel<<<gblocks, 256, 0, 0>>>(C);

    pass2_kernel<<<blocks, 256, 0, 0>>>(edge_attr, edge_index, w_u2, b_u2, out, E);
}

// round 4
// speedup vs baseline: 1.4457x; 1.4457x over previous
#include <cuda_runtime.h>
#include <cstdint>

#define MAXC 10016
#define EMB 32
#define NB 33   // buckets = 32 thresholds + 1

// Scratch (__device__ globals; no allocation allowed)
__device__ __align__(16) float2 d_hist[MAXC * NB];   // per (candidate,bucket): {sum a, count}
__device__ __align__(16) float d_G[MAXC * EMB];      // gather table (q1 folded in)
__device__ float d_p[EMB], d_q[EMB], d_p1[EMB];
__device__ float d_u[EMB];
__device__ __align__(16) float d_W[EMB * EMB];       // w_t2 @ w_u1_bot
__device__ float d_q1v[EMB];
__device__ float d_ts[64];                            // sorted thresholds, padded with +INF
__device__ int   d_perm[EMB];                         // perm[r] = k (rank -> feature)

// ---------------------------------------------------------------------------
// Precompute folded weights + sorted thresholds (tiny, 1 block of 1024)
// ---------------------------------------------------------------------------
__global__ void precompute_kernel(const float* __restrict__ w_v2h,
                                  const float* __restrict__ b_v2h,
                                  const float* __restrict__ w_t1,
                                  const float* __restrict__ b_t1,
                                  const float* __restrict__ w_t2,
                                  const float* __restrict__ b_t2,
                                  const float* __restrict__ w_u1,
                                  const float* __restrict__ b_u1)
{
    __shared__ float tarr[EMB];
    int tid = threadIdx.x;
    int m = tid >> 5, k = tid & 31;

    // W[m][k] = sum_j w_t2[m][j] * w_u1[32+j][k]
    float w = 0.f;
    #pragma unroll
    for (int j = 0; j < EMB; j++)
        w += w_t2[m * EMB + j] * w_u1[(EMB + j) * EMB + k];
    d_W[m * EMB + k] = w;

    if (m == 0) {
        float u = 0.f;
        #pragma unroll
        for (int j = 0; j < EMB; j++)
            u += b_t2[j] * w_u1[(EMB + j) * EMB + k];
        d_u[k] = u;

        float p = 0.f, q = 0.f, p1 = 0.f, q1 = 0.f;
        #pragma unroll
        for (int i = 0; i < EMB; i++) {
            float v = w_v2h[i];
            float b = b_v2h[i];
            p  += v * w_t1[i * EMB + k];
            q  += b * w_t1[i * EMB + k];
            p1 += v * w_u1[i * EMB + k];
            q1 += b * w_u1[i * EMB + k];
        }
        float qe = q + b_t1[k];
        d_p[k]   = p;
        d_q[k]   = qe;
        d_p1[k]  = p1;
        d_q1v[k] = q1 + b_u1[k];
        // threshold: relu(a*p + qe) kinks at a = -qe/p  (p==0 -> +INF sentinel)
        float t = (p != 0.f) ? (-qe / p) : __int_as_float(0x7f800000);
        tarr[k] = t;
    }
    __syncthreads();

    if (tid < 32) {
        float t = tarr[tid];
        int r = 0;
        #pragma unroll
        for (int j = 0; j < 32; j++) {
            float tj = tarr[j];
            r += (tj < t) || (tj == t && j < tid);
        }
        d_ts[r] = t;
        d_perm[r] = tid;
    } else if (tid < 64) {
        d_ts[tid] = __int_as_float(0x7f800000);   // +INF padding for 6-step search
    }
}

// ---------------------------------------------------------------------------
// Pass 1: per-edge bucket(a) via binary search, one red.v2 {a,1} per edge
// ---------------------------------------------------------------------------
__global__ __launch_bounds__(256) void pass1_kernel(
    const float* __restrict__ edge_attr,
    const int* __restrict__ src,
    int E)
{
    __shared__ float ts[64];
    if (threadIdx.x < 64) ts[threadIdx.x] = d_ts[threadIdx.x];
    __syncthreads();

    int e = blockIdx.x * blockDim.x + threadIdx.x;
    if (e >= E) return;

    float a = edge_attr[e];
    int c = src[e];

    // count of sorted thresholds < a  (6-step branchless search over padded 64)
    int pos = 0;
    #pragma unroll
    for (int s = 32; s >= 1; s >>= 1)
        if (ts[pos + s - 1] < a) pos += s;
    // pos in [0, 32]

    float2* addr = d_hist + c * NB + pos;
    asm volatile("red.global.add.v2.f32 [%0], {%1, %2};"
                 :: "l"(addr), "f"(a), "f"(1.0f) : "memory");
}

// ---------------------------------------------------------------------------
// G table: warp per candidate. Shfl-scan buckets -> sumR -> matvec with W.
// G[c][k'] = q1[k'] + cntTot*u[k'] + sum_m sumR[c][m] * W[m][k']
// ---------------------------------------------------------------------------
__global__ __launch_bounds__(256) void gtable_kernel(int C)
{
    __shared__ float sW[EMB * EMB];
    __shared__ float su[EMB], sq1[EMB], sp[EMB], sq[EMB];
    __shared__ int sperm[EMB];
    __shared__ float sR[8][EMB];

    for (int i = threadIdx.x; i < EMB * EMB; i += blockDim.x) sW[i] = d_W[i];
    if (threadIdx.x < EMB) {
        su[threadIdx.x]  = d_u[threadIdx.x];
        sq1[threadIdx.x] = d_q1v[threadIdx.x];
        sp[threadIdx.x]  = d_p[threadIdx.x];
        sq[threadIdx.x]  = d_q[threadIdx.x];
        sperm[threadIdx.x] = d_perm[threadIdx.x];
    }
    __syncthreads();

    int lane = threadIdx.x & 31;
    int wid  = threadIdx.x >> 5;
    int c = blockIdx.x * 8 + wid;
    if (c >= C) return;

    // lane r holds bucket r; bucket 32 loaded broadcast by all lanes
    float2 h   = d_hist[c * NB + lane];
    float2 h32 = d_hist[c * NB + 32];

    float Ps = h.x, Pn = h.y;   // inclusive prefix over buckets 0..lane
    #pragma unroll
    for (int d = 1; d < 32; d <<= 1) {
        float xs = __shfl_up_sync(0xffffffffu, Ps, d);
        float xn = __shfl_up_sync(0xffffffffu, Pn, d);
        if (lane >= d) { Ps += xs; Pn += xn; }
    }
    float Ts = __shfl_sync(0xffffffffu, Ps, 31) + h32.x;
    float Tn = __shfl_sync(0xffffffffu, Pn, 31) + h32.y;

    // lane r <-> threshold rank r <-> feature k = perm[r]
    int k = sperm[lane];
    float p = sp[k], q = sq[k];
    float sumR;
    if (p > 0.f)      sumR = p * (Ts - Ps) + q * (Tn - Pn);  // active: a > t
    else if (p < 0.f) sumR = p * Ps + q * Pn;                // active: a <= t
    else              sumR = Tn * fmaxf(q, 0.f);             // constant
    sR[wid][k] = sumR;   // k is a permutation of lanes: conflict-free
    __syncwarp();

    float acc = sq1[lane] + Tn * su[lane];
    #pragma unroll
    for (int m = 0; m < EMB; m++)
        acc = fmaf(sR[wid][m], sW[m * EMB + lane], acc);
    d_G[c * EMB + lane] = acc;
}

// ---------------------------------------------------------------------------
// Pass 2: warp processes 2 edges/iter. Lane k owns w_u2 column k in regs
// (duplicated f32x2). z-pairs staged in shared, 32 fma.rn.f32x2 per pair.
// ---------------------------------------------------------------------------
__global__ __launch_bounds__(256) void pass2_kernel(
    const float* __restrict__ edge_attr,
    const int* __restrict__ src,
    const float* __restrict__ w_u2,
    const float* __restrict__ b_u2,
    float* __restrict__ out,
    int E)
{
    __shared__ unsigned long long zbuf[8][EMB];

    int lane = threadIdx.x & 31;
    int wid  = threadIdx.x >> 5;
    int gw   = blockIdx.x * 8 + wid;
    int nw   = gridDim.x * 8;

    float p1 = d_p1[lane];

    // lane's w_u2 column, each value duplicated into an f32x2 register
    unsigned long long ww[EMB];
    #pragma unroll
    for (int j = 0; j < EMB; j++) {
        float w = w_u2[j * EMB + lane];
        asm("mov.b64 %0, {%1, %1};" : "=l"(ww[j]) : "f"(w));
    }
    unsigned long long bb;
    {
        float b = b_u2[lane];
        asm("mov.b64 %0, {%1, %1};" : "=l"(bb) : "f"(b));
    }

    int npairs = (E + 1) >> 1;
    for (int pr = gw; pr < npairs; pr += nw) {
        int e0 = pr * 2;
        float a0, a1;
        int c0, c1;
        if (e0 + 1 < E) {
            float2 aa = *(const float2*)(edge_attr + e0);
            int2   cc = *(const int2*)(src + e0);
            a0 = aa.x; a1 = aa.y; c0 = cc.x; c1 = cc.y;
        } else {
            a0 = edge_attr[e0]; a1 = 0.f; c0 = src[e0]; c1 = c0;
        }

        float g0 = d_G[c0 * EMB + lane];
        float g1 = d_G[c1 * EMB + lane];
        float z0 = fmaxf(fmaf(a0, p1, g0), 0.f);
        float z1 = fmaxf(fmaf(a1, p1, g1), 0.f);

        unsigned long long zz;
        asm("mov.b64 %0, {%1, %2};" : "=l"(zz) : "f"(z0), "f"(z1));
        zbuf[wid][lane] = zz;
        __syncwarp();

        unsigned long long acc = bb;
        #pragma unroll
        for (int j = 0; j < EMB; j++) {
            unsigned long long zj = zbuf[wid][j];   // broadcast LDS
            asm("fma.rn.f32x2 %0, %1, %2, %0;" : "+l"(acc) : "l"(zj), "l"(ww[j]));
        }
        __syncwarp();   // protect zbuf before next iteration's store

        float lo, hi;
        asm("mov.b64 {%0, %1}, %2;" : "=f"(lo), "=f"(hi) : "l"(acc));
        out[(size_t)e0 * EMB + lane] = lo;
        if (e0 + 1 < E)
            out[(size_t)(e0 + 1) * EMB + lane] = hi;
    }
}

// ---------------------------------------------------------------------------
extern "C" void kernel_launch(void* const* d_in, const int* in_sizes, int n_in,
                              void* d_out, int out_size)
{
    const float* edge_attr  = (const float*)d_in[0];
    const int*   edge_index = (const int*)d_in[1];   // [2, E] int32; row 0 = src
    const float* w_v2h = (const float*)d_in[3];
    const float* b_v2h = (const float*)d_in[4];
    const float* w_t1  = (const float*)d_in[5];
    const float* b_t1  = (const float*)d_in[6];
    const float* w_t2  = (const float*)d_in[7];
    const float* b_t2  = (const float*)d_in[8];
    const float* w_u1  = (const float*)d_in[9];
    const float* b_u1  = (const float*)d_in[10];
    const float* w_u2  = (const float*)d_in[11];
    const float* b_u2  = (const float*)d_in[12];
    float*       out   = (float*)d_out;

    int E = in_sizes[0];   // edge_attr is [E,1]
    int C = in_sizes[2];   // candidate count

    void* hist_ptr = nullptr;
    cudaGetSymbolAddress(&hist_ptr, d_hist);
    cudaMemsetAsync(hist_ptr, 0, (size_t)C * NB * sizeof(float2), 0);

    precompute_kernel<<<1, 1024, 0, 0>>>(w_v2h, b_v2h, w_t1, b_t1,
                                         w_t2, b_t2, w_u1, b_u1);

    int blocks = (E + 255) / 256;
    pass1_kernel<<<blocks, 256, 0, 0>>>(edge_attr, edge_index, E);

    int gblocks = (C + 7) / 8;
    gtable_kernel<<<gblocks, 256, 0, 0>>>(C);

    pass2_kernel<<<1184, 256, 0, 0>>>(edge_attr, edge_index, w_u2, b_u2, out, E);
}

// round 5
// speedup vs baseline: 1.7539x; 1.2132x over previous
#include <cuda_runtime.h>
#include <cstdint>

#define MAXC 10016
#define EMB 32
#define NB 33   // buckets = 32 thresholds + 1

// Scratch (__device__ globals; no allocation allowed)
__device__ __align__(16) float2 d_hist[MAXC * NB];   // per (candidate,bucket): {sum a, count}
__device__ __align__(16) float d_G[MAXC * EMB];      // gather table (q1 folded in)
__device__ float d_p[EMB], d_q[EMB], d_p1[EMB];
__device__ float d_u[EMB];
__device__ __align__(16) float d_W[EMB * EMB];       // w_t2 @ w_u1_bot
__device__ float d_q1v[EMB];
__device__ float d_ts[64];                            // sorted thresholds, padded with +INF
__device__ int   d_perm[EMB];                         // perm[r] = k (rank -> feature)

// ---------------------------------------------------------------------------
// Precompute folded weights + sorted thresholds (tiny, 1 block of 1024)
// ---------------------------------------------------------------------------
__global__ void precompute_kernel(const float* __restrict__ w_v2h,
                                  const float* __restrict__ b_v2h,
                                  const float* __restrict__ w_t1,
                                  const float* __restrict__ b_t1,
                                  const float* __restrict__ w_t2,
                                  const float* __restrict__ b_t2,
                                  const float* __restrict__ w_u1,
                                  const float* __restrict__ b_u1)
{
    __shared__ float tarr[EMB];
    int tid = threadIdx.x;
    int m = tid >> 5, k = tid & 31;

    // W[m][k] = sum_j w_t2[m][j] * w_u1[32+j][k]
    float w = 0.f;
    #pragma unroll
    for (int j = 0; j < EMB; j++)
        w += w_t2[m * EMB + j] * w_u1[(EMB + j) * EMB + k];
    d_W[m * EMB + k] = w;

    if (m == 0) {
        float u = 0.f;
        #pragma unroll
        for (int j = 0; j < EMB; j++)
            u += b_t2[j] * w_u1[(EMB + j) * EMB + k];
        d_u[k] = u;

        float p = 0.f, q = 0.f, p1 = 0.f, q1 = 0.f;
        #pragma unroll
        for (int i = 0; i < EMB; i++) {
            float v = w_v2h[i];
            float b = b_v2h[i];
            p  += v * w_t1[i * EMB + k];
            q  += b * w_t1[i * EMB + k];
            p1 += v * w_u1[i * EMB + k];
            q1 += b * w_u1[i * EMB + k];
        }
        float qe = q + b_t1[k];
        d_p[k]   = p;
        d_q[k]   = qe;
        d_p1[k]  = p1;
        d_q1v[k] = q1 + b_u1[k];
        // threshold: relu(a*p + qe) kinks at a = -qe/p  (p==0 -> +INF sentinel)
        float t = (p != 0.f) ? (-qe / p) : __int_as_float(0x7f800000);
        tarr[k] = t;
    }
    __syncthreads();

    if (tid < 32) {
        float t = tarr[tid];
        int r = 0;
        #pragma unroll
        for (int j = 0; j < 32; j++) {
            float tj = tarr[j];
            r += (tj < t) || (tj == t && j < tid);
        }
        d_ts[r] = t;
        d_perm[r] = tid;
    } else if (tid < 64) {
        d_ts[tid] = __int_as_float(0x7f800000);   // +INF padding for 6-step search
    }
}

// ---------------------------------------------------------------------------
// Pass 1: per-edge bucket(a) via binary search, one red.v2 {a,1} per edge
// ---------------------------------------------------------------------------
__global__ __launch_bounds__(256) void pass1_kernel(
    const float* __restrict__ edge_attr,
    const int* __restrict__ src,
    int E)
{
    __shared__ float ts[64];
    if (threadIdx.x < 64) ts[threadIdx.x] = d_ts[threadIdx.x];
    __syncthreads();

    int e = blockIdx.x * blockDim.x + threadIdx.x;
    if (e >= E) return;

    float a = edge_attr[e];
    int c = src[e];

    // count of sorted thresholds < a  (6-step branchless search over padded 64)
    int pos = 0;
    #pragma unroll
    for (int s = 32; s >= 1; s >>= 1)
        if (ts[pos + s - 1] < a) pos += s;
    // pos in [0, 32]

    float2* addr = d_hist + c * NB + pos;
    asm volatile("red.global.add.v2.f32 [%0], {%1, %2};"
                 :: "l"(addr), "f"(a), "f"(1.0f) : "memory");
}

// ---------------------------------------------------------------------------
// G table: warp per candidate. Shfl-scan buckets -> sumR -> matvec with W.
// ---------------------------------------------------------------------------
__global__ __launch_bounds__(256) void gtable_kernel(int C)
{
    __shared__ float sW[EMB * EMB];
    __shared__ float su[EMB], sq1[EMB], sp[EMB], sq[EMB];
    __shared__ int sperm[EMB];
    __shared__ float sR[8][EMB];

    for (int i = threadIdx.x; i < EMB * EMB; i += blockDim.x) sW[i] = d_W[i];
    if (threadIdx.x < EMB) {
        su[threadIdx.x]  = d_u[threadIdx.x];
        sq1[threadIdx.x] = d_q1v[threadIdx.x];
        sp[threadIdx.x]  = d_p[threadIdx.x];
        sq[threadIdx.x]  = d_q[threadIdx.x];
        sperm[threadIdx.x] = d_perm[threadIdx.x];
    }
    __syncthreads();

    int lane = threadIdx.x & 31;
    int wid  = threadIdx.x >> 5;
    int c = blockIdx.x * 8 + wid;
    if (c >= C) return;

    float2 h   = d_hist[c * NB + lane];
    float2 h32 = d_hist[c * NB + 32];

    float Ps = h.x, Pn = h.y;   // inclusive prefix over buckets 0..lane
    #pragma unroll
    for (int d = 1; d < 32; d <<= 1) {
        float xs = __shfl_up_sync(0xffffffffu, Ps, d);
        float xn = __shfl_up_sync(0xffffffffu, Pn, d);
        if (lane >= d) { Ps += xs; Pn += xn; }
    }
    float Ts = __shfl_sync(0xffffffffu, Ps, 31) + h32.x;
    float Tn = __shfl_sync(0xffffffffu, Pn, 31) + h32.y;

    int k = sperm[lane];
    float p = sp[k], q = sq[k];
    float sumR;
    if (p > 0.f)      sumR = p * (Ts - Ps) + q * (Tn - Pn);  // active: a > t
    else if (p < 0.f) sumR = p * Ps + q * Pn;                // active: a <= t
    else              sumR = Tn * fmaxf(q, 0.f);             // constant
    sR[wid][k] = sumR;
    __syncwarp();

    float acc = sq1[lane] + Tn * su[lane];
    #pragma unroll
    for (int m = 0; m < EMB; m++)
        acc = fmaf(sR[wid][m], sW[m * EMB + lane], acc);
    d_G[c * EMB + lane] = acc;
}

// ---------------------------------------------------------------------------
// Pass 2: warp processes 8 edges/iter. Lane k owns w_u2 column k duplicated
// into f32x2 regs. z staged as 4 u64 per lane (STS.128 x2), inner loop does
// 2 broadcast LDS.128 + 4 independent fma.rn.f32x2 per j.
// ---------------------------------------------------------------------------
__global__ __launch_bounds__(256, 2) void pass2_kernel(
    const float* __restrict__ edge_attr,
    const int* __restrict__ src,
    const float* __restrict__ w_u2,
    const float* __restrict__ b_u2,
    float* __restrict__ out,
    int E)
{
    // 48B row stride: 16B-aligned for STS/LDS.128, conflict-free store phases
    __shared__ __align__(16) unsigned long long zbuf[8][EMB][6];

    int lane = threadIdx.x & 31;
    int wid  = threadIdx.x >> 5;
    int gw   = blockIdx.x * 8 + wid;
    int nw   = gridDim.x * 8;

    float p1 = d_p1[lane];

    unsigned long long ww[EMB];
    #pragma unroll
    for (int j = 0; j < EMB; j++) {
        float w = w_u2[j * EMB + lane];
        asm("mov.b64 %0, {%1, %1};" : "=l"(ww[j]) : "f"(w));
    }
    unsigned long long bb;
    {
        float b = b_u2[lane];
        asm("mov.b64 %0, {%1, %1};" : "=l"(bb) : "f"(b));
    }

    int ngroups = (E + 7) >> 3;
    for (int g = gw; g < ngroups; g += nw) {
        int e0 = g * 8;
        float av[8];
        int   cv[8];
        bool full = (e0 + 8 <= E);
        if (full) {
            float4 aA = *(const float4*)(edge_attr + e0);
            float4 aB = *(const float4*)(edge_attr + e0 + 4);
            int4   cA = *(const int4*)(src + e0);
            int4   cB = *(const int4*)(src + e0 + 4);
            av[0]=aA.x; av[1]=aA.y; av[2]=aA.z; av[3]=aA.w;
            av[4]=aB.x; av[5]=aB.y; av[6]=aB.z; av[7]=aB.w;
            cv[0]=cA.x; cv[1]=cA.y; cv[2]=cA.z; cv[3]=cA.w;
            cv[4]=cB.x; cv[5]=cB.y; cv[6]=cB.z; cv[7]=cB.w;
        } else {
            #pragma unroll
            for (int i = 0; i < 8; i++) {
                int e = (e0 + i < E) ? (e0 + i) : (E - 1);
                av[i] = edge_attr[e];
                cv[i] = src[e];
            }
        }

        float z[8];
        #pragma unroll
        for (int i = 0; i < 8; i++)
            z[i] = fmaxf(fmaf(av[i], p1, d_G[cv[i] * EMB + lane]), 0.f);

        unsigned long long zp0, zp1, zp2, zp3;
        asm("mov.b64 %0, {%1, %2};" : "=l"(zp0) : "f"(z[0]), "f"(z[1]));
        asm("mov.b64 %0, {%1, %2};" : "=l"(zp1) : "f"(z[2]), "f"(z[3]));
        asm("mov.b64 %0, {%1, %2};" : "=l"(zp2) : "f"(z[4]), "f"(z[5]));
        asm("mov.b64 %0, {%1, %2};" : "=l"(zp3) : "f"(z[6]), "f"(z[7]));

        ulonglong2* dst = (ulonglong2*)&zbuf[wid][lane][0];
        dst[0] = make_ulonglong2(zp0, zp1);
        dst[1] = make_ulonglong2(zp2, zp3);
        __syncwarp();

        unsigned long long acc0 = bb, acc1 = bb, acc2 = bb, acc3 = bb;
        #pragma unroll
        for (int j = 0; j < EMB; j++) {
            const ulonglong2* row = (const ulonglong2*)&zbuf[wid][j][0];
            ulonglong2 r0 = row[0];   // z pairs (e0,e1), (e2,e3)
            ulonglong2 r1 = row[1];   // z pairs (e4,e5), (e6,e7)
            asm("fma.rn.f32x2 %0, %1, %2, %0;" : "+l"(acc0) : "l"(r0.x), "l"(ww[j]));
            asm("fma.rn.f32x2 %0, %1, %2, %0;" : "+l"(acc1) : "l"(r0.y), "l"(ww[j]));
            asm("fma.rn.f32x2 %0, %1, %2, %0;" : "+l"(acc2) : "l"(r1.x), "l"(ww[j]));
            asm("fma.rn.f32x2 %0, %1, %2, %0;" : "+l"(acc3) : "l"(r1.y), "l"(ww[j]));
        }
        __syncwarp();   // protect zbuf before next iteration's store

        float o[8];
        asm("mov.b64 {%0, %1}, %2;" : "=f"(o[0]), "=f"(o[1]) : "l"(acc0));
        asm("mov.b64 {%0, %1}, %2;" : "=f"(o[2]), "=f"(o[3]) : "l"(acc1));
        asm("mov.b64 {%0, %1}, %2;" : "=f"(o[4]), "=f"(o[5]) : "l"(acc2));
        asm("mov.b64 {%0, %1}, %2;" : "=f"(o[6]), "=f"(o[7]) : "l"(acc3));

        float* ob = out + (size_t)e0 * EMB + lane;
        if (full) {
            #pragma unroll
            for (int i = 0; i < 8; i++)
                ob[i * EMB] = o[i];
        } else {
            #pragma unroll
            for (int i = 0; i < 8; i++)
                if (e0 + i < E) ob[i * EMB] = o[i];
        }
    }
}

// ---------------------------------------------------------------------------
extern "C" void kernel_launch(void* const* d_in, const int* in_sizes, int n_in,
                              void* d_out, int out_size)
{
    const float* edge_attr  = (const float*)d_in[0];
    const int*   edge_index = (const int*)d_in[1];   // [2, E] int32; row 0 = src
    const float* w_v2h = (const float*)d_in[3];
    const float* b_v2h = (const float*)d_in[4];
    const float* w_t1  = (const float*)d_in[5];
    const float* b_t1  = (const float*)d_in[6];
    const float* w_t2  = (const float*)d_in[7];
    const float* b_t2  = (const float*)d_in[8];
    const float* w_u1  = (const float*)d_in[9];
    const float* b_u1  = (const float*)d_in[10];
    const float* w_u2  = (const float*)d_in[11];
    const float* b_u2  = (const float*)d_in[12];
    float*       out   = (float*)d_out;

    int E = in_sizes[0];   // edge_attr is [E,1]
    int C = in_sizes[2];   // candidate count

    void* hist_ptr = nullptr;
    cudaGetSymbolAddress(&hist_ptr, d_hist);
    cudaMemsetAsync(hist_ptr, 0, (size_t)C * NB * sizeof(float2), 0);

    precompute_kernel<<<1, 1024, 0, 0>>>(w_v2h, b_v2h, w_t1, b_t1,
                                         w_t2, b_t2, w_u1, b_u1);

    int blocks = (E + 255) / 256;
    pass1_kernel<<<blocks, 256, 0, 0>>>(edge_attr, edge_index, E);

    int gblocks = (C + 7) / 8;
    gtable_kernel<<<gblocks, 256, 0, 0>>>(C);

    pass2_kernel<<<1184, 256, 0, 0>>>(edge_attr, edge_index, w_u2, b_u2, out, E);
}

// round 7
// speedup vs baseline: 2.5786x; 1.4702x over previous
#include <cuda_runtime.h>
#include <cstdint>

#define MAXC 10016
#define EMB 32
#define NB 33   // buckets = 32 thresholds + 1

// Scratch (__device__ globals; no allocation allowed)
__device__ __align__(16) float2 d_hist[MAXC * NB];    // per (candidate,bucket): {sum a, count}
__device__ __align__(16) float d_G[MAXC * EMB];       // pre-activation bias per candidate
__device__ float d_p[EMB], d_q[EMB], d_p1[EMB];
__device__ float d_u[EMB];
__device__ __align__(16) float d_W[EMB * EMB];        // w_t2 @ w_u1_bot
__device__ float d_q1v[EMB];
__device__ float d_ts[64];                             // sorted global thresholds (+INF pad)
__device__ int   d_perm[EMB];
// Piecewise-linear output table: out = U + a*V per (candidate, bucket)
__device__ __align__(16) float2 d_UV[(size_t)MAXC * NB * EMB];   // 84.6 MB, L2-resident
__device__ __align__(16) float  d_knee[MAXC * EMB];              // per-candidate knees

// ---------------------------------------------------------------------------
// Precompute folded weights + sorted global thresholds (tiny, 1 block)
// ---------------------------------------------------------------------------
__global__ void precompute_kernel(const float* __restrict__ w_v2h,
                                  const float* __restrict__ b_v2h,
                                  const float* __restrict__ w_t1,
                                  const float* __restrict__ b_t1,
                                  const float* __restrict__ w_t2,
                                  const float* __restrict__ b_t2,
                                  const float* __restrict__ w_u1,
                                  const float* __restrict__ b_u1)
{
    __shared__ float tarr[EMB];
    int tid = threadIdx.x;
    int m = tid >> 5, k = tid & 31;

    float w = 0.f;
    #pragma unroll
    for (int j = 0; j < EMB; j++)
        w += w_t2[m * EMB + j] * w_u1[(EMB + j) * EMB + k];
    d_W[m * EMB + k] = w;

    if (m == 0) {
        float u = 0.f;
        #pragma unroll
        for (int j = 0; j < EMB; j++)
            u += b_t2[j] * w_u1[(EMB + j) * EMB + k];
        d_u[k] = u;

        float p = 0.f, q = 0.f, p1 = 0.f, q1 = 0.f;
        #pragma unroll
        for (int i = 0; i < EMB; i++) {
            float v = w_v2h[i];
            float b = b_v2h[i];
            p  += v * w_t1[i * EMB + k];
            q  += b * w_t1[i * EMB + k];
            p1 += v * w_u1[i * EMB + k];
            q1 += b * w_u1[i * EMB + k];
        }
        float qe = q + b_t1[k];
        d_p[k]   = p;
        d_q[k]   = qe;
        d_p1[k]  = p1;
        d_q1v[k] = q1 + b_u1[k];
        float t = (p != 0.f) ? (-qe / p) : __int_as_float(0x7f800000);
        tarr[k] = t;
    }
    __syncthreads();

    if (tid < 32) {
        float t = tarr[tid];
        int r = 0;
        #pragma unroll
        for (int j = 0; j < 32; j++) {
            float tj = tarr[j];
            r += (tj < t) || (tj == t && j < tid);
        }
        d_ts[r] = t;
        d_perm[r] = tid;
    } else if (tid < 64) {
        d_ts[tid] = __int_as_float(0x7f800000);
    }
}

// ---------------------------------------------------------------------------
// Pass 1: per-edge bucket(a) via binary search, one red.v2 {a,1} per edge
// ---------------------------------------------------------------------------
__global__ __launch_bounds__(256) void pass1_kernel(
    const float* __restrict__ edge_attr,
    const int* __restrict__ src,
    int E)
{
    __shared__ float ts[64];
    if (threadIdx.x < 64) ts[threadIdx.x] = d_ts[threadIdx.x];
    __syncthreads();

    int e = blockIdx.x * blockDim.x + threadIdx.x;
    if (e >= E) return;

    float a = edge_attr[e];
    int c = src[e];

    int pos = 0;
    #pragma unroll
    for (int s = 32; s >= 1; s >>= 1)
        if (ts[pos + s - 1] < a) pos += s;

    float2* addr = d_hist + c * NB + pos;
    asm volatile("red.global.add.v2.f32 [%0], {%1, %2};"
                 :: "l"(addr), "f"(a), "f"(1.0f) : "memory");
}

// ---------------------------------------------------------------------------
// G table: warp per candidate. Shfl-scan buckets -> sumR -> matvec with W.
// ---------------------------------------------------------------------------
__global__ __launch_bounds__(256) void gtable_kernel(int C)
{
    __shared__ float sW[EMB * EMB];
    __shared__ float su[EMB], sq1[EMB], sp[EMB], sq[EMB];
    __shared__ int sperm[EMB];
    __shared__ float sR[8][EMB];

    for (int i = threadIdx.x; i < EMB * EMB; i += blockDim.x) sW[i] = d_W[i];
    if (threadIdx.x < EMB) {
        su[threadIdx.x]  = d_u[threadIdx.x];
        sq1[threadIdx.x] = d_q1v[threadIdx.x];
        sp[threadIdx.x]  = d_p[threadIdx.x];
        sq[threadIdx.x]  = d_q[threadIdx.x];
        sperm[threadIdx.x] = d_perm[threadIdx.x];
    }
    __syncthreads();

    int lane = threadIdx.x & 31;
    int wid  = threadIdx.x >> 5;
    int c = blockIdx.x * 8 + wid;
    if (c >= C) return;

    float2 h   = d_hist[c * NB + lane];
    float2 h32 = d_hist[c * NB + 32];

    float Ps = h.x, Pn = h.y;
    #pragma unroll
    for (int d = 1; d < 32; d <<= 1) {
        float xs = __shfl_up_sync(0xffffffffu, Ps, d);
        float xn = __shfl_up_sync(0xffffffffu, Pn, d);
        if (lane >= d) { Ps += xs; Pn += xn; }
    }
    float Ts = __shfl_sync(0xffffffffu, Ps, 31) + h32.x;
    float Tn = __shfl_sync(0xffffffffu, Pn, 31) + h32.y;

    int k = sperm[lane];
    float p = sp[k], q = sq[k];
    float sumR;
    if (p > 0.f)      sumR = p * (Ts - Ps) + q * (Tn - Pn);
    else if (p < 0.f) sumR = p * Ps + q * Pn;
    else              sumR = Tn * fmaxf(q, 0.f);
    sR[wid][k] = sumR;
    __syncwarp();

    float acc = sq1[lane] + Tn * su[lane];
    #pragma unroll
    for (int m = 0; m < EMB; m++)
        acc = fmaf(sR[wid][m], sW[m * EMB + lane], acc);
    d_G[c * EMB + lane] = acc;
}

// ---------------------------------------------------------------------------
// UV build: warp per candidate. out(a) = U + a*V piecewise-linear in a.
// Knees t_j = -G[c,j]/p1_j; crossing knee rank b-1 toggles one feature.
// b_u2 folded into U. 33 buckets x 32 k per candidate.
// ---------------------------------------------------------------------------
__global__ __launch_bounds__(256) void uvbuild_kernel(
    const float* __restrict__ w_u2,
    const float* __restrict__ b_u2,
    int C)
{
    __shared__ float sw2[EMB * EMB];     // w_u2[j][k]
    __shared__ float sp1[EMB], sb[EMB];
    __shared__ float st[8][EMB];         // knees per warp
    __shared__ float sG[8][EMB];
    __shared__ int   sjb[8][EMB];        // rank -> feature

    for (int i = threadIdx.x; i < EMB * EMB; i += blockDim.x) sw2[i] = w_u2[i];
    if (threadIdx.x < EMB) {
        sp1[threadIdx.x] = d_p1[threadIdx.x];
        sb[threadIdx.x]  = b_u2[threadIdx.x];
    }
    __syncthreads();

    int lane = threadIdx.x & 31;
    int wid  = threadIdx.x >> 5;
    int c = blockIdx.x * 8 + wid;
    if (c >= C) return;

    float Gk  = d_G[c * EMB + lane];
    float p1k = sp1[lane];
    float t = (p1k != 0.f) ? (-Gk / p1k) : __int_as_float(0x7f800000);
    d_knee[c * EMB + lane] = t;

    st[wid][lane] = t;
    sG[wid][lane] = Gk;
    __syncwarp();

    int r = 0;
    #pragma unroll
    for (int j = 0; j < EMB; j++) {
        float tj = st[wid][j];
        r += (tj < t) || (tj == t && j < lane);
    }
    sjb[wid][r] = lane;
    __syncwarp();

    // base: bucket 0 (a below all knees): active iff p1<0, or p1==0 && G>0
    float U = sb[lane];
    float V = 0.f;
    #pragma unroll
    for (int j = 0; j < EMB; j++) {
        float pj = sp1[j];
        float gj = sG[wid][j];
        bool act = (pj < 0.f) || (pj == 0.f && gj > 0.f);
        if (act) {
            U = fmaf(gj, sw2[j * EMB + lane], U);
            V = fmaf(pj, sw2[j * EMB + lane], V);
        }
    }

    float2* uvrow = d_UV + (size_t)c * NB * EMB;
    uvrow[lane] = make_float2(U, V);

    for (int b = 1; b < NB; b++) {
        int j = sjb[wid][b - 1];
        float pj = sp1[j];
        float s = (pj > 0.f) ? 1.f : ((pj < 0.f) ? -1.f : 0.f);
        float wjk = sw2[j * EMB + lane];
        U = fmaf(s * sG[wid][j], wjk, U);
        V = fmaf(s * pj, wjk, V);
        uvrow[b * EMB + lane] = make_float2(U, V);
    }
}

// ---------------------------------------------------------------------------
// Pass 2: warp handles 8 edges/iter. Per edge: knee row (128B) -> ballot ->
// bucket, UV row (256B) gather, out = fma(a, V, U), streaming store.
// ---------------------------------------------------------------------------
__global__ __launch_bounds__(256) void pass2_kernel(
    const float* __restrict__ edge_attr,
    const int* __restrict__ src,
    float* __restrict__ out,
    int E)
{
    int lane = threadIdx.x & 31;
    int wid  = threadIdx.x >> 5;
    int gw   = blockIdx.x * 8 + wid;
    int nw   = gridDim.x * 8;

    int ngroups = (E + 7) >> 3;
    for (int g = gw; g < ngroups; g += nw) {
        int e0 = g * 8;
        float av[8];
        int   cv[8];
        bool full = (e0 + 8 <= E);
        if (full) {
            float4 aA = *(const float4*)(edge_attr + e0);
            float4 aB = *(const float4*)(edge_attr + e0 + 4);
            int4   cA = *(const int4*)(src + e0);
            int4   cB = *(const int4*)(src + e0 + 4);
            av[0]=aA.x; av[1]=aA.y; av[2]=aA.z; av[3]=aA.w;
            av[4]=aB.x; av[5]=aB.y; av[6]=aB.z; av[7]=aB.w;
            cv[0]=cA.x; cv[1]=cA.y; cv[2]=cA.z; cv[3]=cA.w;
            cv[4]=cB.x; cv[5]=cB.y; cv[6]=cB.z; cv[7]=cB.w;
        } else {
            #pragma unroll
            for (int i = 0; i < 8; i++) {
                int e = (e0 + i < E) ? (e0 + i) : (E - 1);
                av[i] = edge_attr[e];
                cv[i] = src[e];
            }
        }

        // knee rows (coalesced 128B each), MLP=8
        float tk[8];
        #pragma unroll
        for (int i = 0; i < 8; i++)
            tk[i] = d_knee[cv[i] * EMB + lane];

        int bk[8];
        #pragma unroll
        for (int i = 0; i < 8; i++)
            bk[i] = __popc(__ballot_sync(0xffffffffu, tk[i] < av[i]));

        // UV rows (coalesced 256B each), MLP=8
        float2 uv[8];
        #pragma unroll
        for (int i = 0; i < 8; i++)
            uv[i] = d_UV[((size_t)cv[i] * NB + bk[i]) * EMB + lane];

        float* ob = out + (size_t)e0 * EMB + lane;
        if (full) {
            #pragma unroll
            for (int i = 0; i < 8; i++) {
                float o = fmaf(av[i], uv[i].y, uv[i].x);
                asm volatile("st.global.cs.f32 [%0], %1;"
                             :: "l"(ob + i * EMB), "f"(o) : "memory");
            }
        } else {
            #pragma unroll
            for (int i = 0; i < 8; i++) {
                if (e0 + i < E) {
                    float o = fmaf(av[i], uv[i].y, uv[i].x);
                    asm volatile("st.global.cs.f32 [%0], %1;"
                                 :: "l"(ob + i * EMB), "f"(o) : "memory");
                }
            }
        }
    }
}

// ---------------------------------------------------------------------------
extern "C" void kernel_launch(void* const* d_in, const int* in_sizes, int n_in,
                              void* d_out, int out_size)
{
    const float* edge_attr  = (const float*)d_in[0];
    const int*   edge_index = (const int*)d_in[1];   // [2, E] int32; row 0 = src
    const float* w_v2h = (const float*)d_in[3];
    const float* b_v2h = (const float*)d_in[4];
    const float* w_t1  = (const float*)d_in[5];
    const float* b_t1  = (const float*)d_in[6];
    const float* w_t2  = (const float*)d_in[7];
    const float* b_t2  = (const float*)d_in[8];
    const float* w_u1  = (const float*)d_in[9];
    const float* b_u1  = (const float*)d_in[10];
    const float* w_u2  = (const float*)d_in[11];
    const float* b_u2  = (const float*)d_in[12];
    float*       out   = (float*)d_out;

    int E = in_sizes[0];
    int C = in_sizes[2];

    void* hist_ptr = nullptr;
    cudaGetSymbolAddress(&hist_ptr, d_hist);
    cudaMemsetAsync(hist_ptr, 0, (size_t)C * NB * sizeof(float2), 0);

    precompute_kernel<<<1, 1024, 0, 0>>>(w_v2h, b_v2h, w_t1, b_t1,
                                         w_t2, b_t2, w_u1, b_u1);

    int blocks = (E + 255) / 256;
    pass1_kernel<<<blocks, 256, 0, 0>>>(edge_attr, edge_index, E);

    int gblocks = (C + 7) / 8;
    gtable_kernel<<<gblocks, 256, 0, 0>>>(C);
    uvbuild_kernel<<<gblocks, 256, 0, 0>>>(w_u2, b_u2, C);

    pass2_kernel<<<1184, 256, 0, 0>>>(edge_attr, edge_index, out, E);
}